// round 13
// baseline (speedup 1.0000x reference)
#include <cuda_runtime.h>
#include <cuda_fp16.h>
#include <math.h>

#define BH   64      // B*H
#define NB   32      // buckets
#define BSZ  128     // tokens per bucket
#define DHD  64      // head dim
#define TPB  (BSZ*DHD)   // 8192 elems per bucket tile

typedef unsigned long long u64;
typedef unsigned int u32;

// ---- packed f32x2 helpers ----
__device__ __forceinline__ u64 f2_fma(u64 a, u64 b, u64 c) {
    u64 d; asm("fma.rn.f32x2 %0,%1,%2,%3;" : "=l"(d) : "l"(a), "l"(b), "l"(c)); return d;
}
__device__ __forceinline__ u64 f2_pack(float lo, float hi) {
    u64 d; asm("mov.b64 %0,{%1,%2};" : "=l"(d) : "f"(lo), "f"(hi)); return d;
}
__device__ __forceinline__ float2 f2_unpack(u64 v) {
    float2 r; asm("mov.b64 {%0,%1},%2;" : "=f"(r.x), "=f"(r.y) : "l"(v)); return r;
}

// ---- fp16 helpers ----
__device__ __forceinline__ u32 h2pack(float lo, float hi) {
    __half2 h = __floats2half2_rn(lo, hi);
    return *(u32*)&h;
}
__device__ __forceinline__ float2 h2unpack(u32 v) {
    __half2 h = *(__half2*)&v;
    return __half22float2(h);
}
// packed fp16 2^x (one MUFU op for two lanes)
__device__ __forceinline__ u32 h2ex2(u32 s) {
    u32 p; asm("ex2.approx.f16x2 %0,%1;" : "=r"(p) : "r"(s)); return p;
}

// ---- fp16 mma m16n8k16, f32 accumulate ----
__device__ __forceinline__ void mma_f16(float& d0, float& d1, float& d2, float& d3,
                                        u32 a0, u32 a1, u32 a2, u32 a3,
                                        u32 b0, u32 b1) {
    asm("mma.sync.aligned.m16n8k16.row.col.f32.f16.f16.f32 "
        "{%0,%1,%2,%3},{%4,%5,%6,%7},{%8,%9},{%0,%1,%2,%3};"
        : "+f"(d0), "+f"(d1), "+f"(d2), "+f"(d3)
        : "r"(a0), "r"(a1), "r"(a2), "r"(a3), "r"(b0), "r"(b1));
}

// ---- ldmatrix ----
__device__ __forceinline__ void ldsm_x4(u32& r0, u32& r1, u32& r2, u32& r3, u32 addr) {
    asm volatile("ldmatrix.sync.aligned.m8n8.x4.shared.b16 {%0,%1,%2,%3},[%4];"
                 : "=r"(r0), "=r"(r1), "=r"(r2), "=r"(r3) : "r"(addr));
}
__device__ __forceinline__ void ldsm_x4_t(u32& r0, u32& r1, u32& r2, u32& r3, u32 addr) {
    asm volatile("ldmatrix.sync.aligned.m8n8.x4.trans.shared.b16 {%0,%1,%2,%3},[%4];"
                 : "=r"(r0), "=r"(r1), "=r"(r2), "=r"(r3) : "r"(addr));
}

// ---- cp.async ----
__device__ __forceinline__ void cp_async16(u32 smem_addr, const void* gptr) {
    asm volatile("cp.async.cg.shared.global [%0], [%1], 16;"
                 :: "r"(smem_addr), "l"(gptr));
}
__device__ __forceinline__ void cp_commit() {
    asm volatile("cp.async.commit_group;");
}
template<int N> __device__ __forceinline__ void cp_wait() {
    asm volatile("cp.async.wait_group %0;" :: "n"(N));
}

// Scratch (allocation-free rule: __device__ globals). fp16 stored as packed u32.
__device__ float g_R[BH*NB*NB];
__device__ float g_bkr[BH*NB*DHD];
__device__ u32 g_k16  [(size_t)BH*NB*TPB/2];
__device__ u32 g_v16  [(size_t)BH*NB*TPB/2];
__device__ u32 g_kre16[(size_t)BH*NB*TPB/2];
__device__ u32 g_vre16[(size_t)BH*NB*TPB/2];

// ---------------------------------------------------------------------------
// Kernel 0: bucket key sums + fp16 conversion of K and V.  (R12 exact.)
// ---------------------------------------------------------------------------
__global__ void __launch_bounds__(256)
cvt_bucket_kernel(const float* __restrict__ k, const float* __restrict__ v)
{
    int u  = blockIdx.x;
    int bh = blockIdx.y;
    int tid = threadIdx.x;

    __shared__ float2 red[8][32];

    size_t base2 = (size_t)(bh * NB + u) * (TPB / 2);
    const float2* k2 = (const float2*)k + base2;
    const float2* v2 = (const float2*)v + base2;
    u32* ko = g_k16 + base2;
    u32* vo = g_v16 + base2;

    float2 s = make_float2(0.f, 0.f);
    #pragma unroll
    for (int j = 0; j < 16; j++) {
        int f = tid + j * 256;
        float2 x = k2[f];
        s.x += x.x; s.y += x.y;
        ko[f] = h2pack(x.x, x.y);
    }
    red[tid >> 5][tid & 31] = s;

    #pragma unroll
    for (int j = 0; j < 16; j++) {
        int f = tid + j * 256;
        float2 x = v2[f];
        vo[f] = h2pack(x.x, x.y);
    }
    __syncthreads();
    if (tid < 32) {
        float2 t = make_float2(0.f, 0.f);
        #pragma unroll
        for (int w = 0; w < 8; w++) { t.x += red[w][tid].x; t.y += red[w][tid].y; }
        g_bkr[(bh * NB + u) * DHD + 2 * tid]     = t.x;
        g_bkr[(bh * NB + u) * DHD + 2 * tid + 1] = t.y;
    }
}

// ---------------------------------------------------------------------------
// Kernel 1: routing -> 7 Sinkhorn iters -> exp -> strict lower tri. (R12.)
// ---------------------------------------------------------------------------
__global__ void __launch_bounds__(1024)
sinkhorn_kernel(const float* __restrict__ sort_w,
                const float* __restrict__ gum)
{
    int bh  = blockIdx.x;
    int tid = threadIdx.x;

    __shared__ float bkr[NB][DHD];
    __shared__ float ews[DHD][NB];
    __shared__ float smx[NB][NB + 1];

    int h = bh & 15;
    #pragma unroll
    for (int rep = 0; rep < 2; rep++) {
        int idx = tid + rep * 1024;
        ((float*)bkr)[idx] = g_bkr[bh * (NB * DHD) + idx];
        ((float*)ews)[idx] = sort_w[h * (DHD * NB) + idx];
    }
    __syncthreads();

    int u = tid >> 5;
    int j = tid & 31;

    float r = 0.f;
    #pragma unroll
    for (int d = 0; d < DHD; d++) r += bkr[u][d] * ews[d][j];
    r = logf(fmaxf(r, 0.f) + 1e-6f);
    r = (r + gum[bh * 1024 + tid]) * (1.0f / 0.75f);

    for (int it = 0; it < 7; it++) {
        float m = r;
        #pragma unroll
        for (int off = 16; off > 0; off >>= 1)
            m = fmaxf(m, __shfl_xor_sync(0xffffffffu, m, off));
        float se = __expf(r - m);
        #pragma unroll
        for (int off = 16; off > 0; off >>= 1)
            se += __shfl_xor_sync(0xffffffffu, se, off);
        r -= m + logf(se);

        smx[u][j] = r;
        __syncthreads();
        float cm = -3.0e38f;
        #pragma unroll
        for (int vv = 0; vv < NB; vv++) cm = fmaxf(cm, smx[vv][j]);
        float cs = 0.f;
        #pragma unroll
        for (int vv = 0; vv < NB; vv++) cs += __expf(smx[vv][j] - cm);
        r -= cm + logf(cs);
        __syncthreads();
    }

    r = __expf(r);
    if (j >= u) r = 0.f;
    g_R[bh * 1024 + tid] = r;
}

// ---------------------------------------------------------------------------
// Kernel 2: soft permutation  x_re = R @ Xmat.  (R12 exact: grid-level
// triangular split, blockIdx.z = half*2 + kv decode below.)
// ---------------------------------------------------------------------------
__global__ void __launch_bounds__(256)
permute_kernel()
{
    int tilec = blockIdx.x;          // 0..15
    int bh    = blockIdx.y;
    int kv    = blockIdx.z & 1;      // 0 = K, 1 = V
    int half  = blockIdx.z >> 1;     // 0 = rows 0..15, 1 = rows 16..31
    int tid   = threadIdx.x;

    __shared__ u64 RsP[NB][16];      // RsP[v][p] = (R[2p][v], R[2p+1][v])
    const float* gR = g_R + bh * 1024;
    #pragma unroll
    for (int rep = 0; rep < 2; rep++) {
        int idx = tid + rep * 256;
        int vv = idx >> 4, p = idx & 15;
        RsP[vv][p] = f2_pack(gR[(2*p) * NB + vv], gR[(2*p+1) * NB + vv]);
    }
    __syncthreads();

    const u32* src = kv ? g_v16   : g_k16;
    u32*       dst = kv ? g_vre16 : g_kre16;

    size_t base2 = (size_t)bh * NB * (TPB/2) + (size_t)tilec * 256 + tid;

    if (half == 0) {
        u64 acc[8][2];
        #pragma unroll
        for (int p = 0; p < 8; p++) { acc[p][0] = 0ULL; acc[p][1] = 0ULL; }
        #pragma unroll
        for (int vv = 0; vv < 15; vv++) {
            float2 x = h2unpack(src[base2 + (size_t)vv * (TPB/2)]);
            u64 xa = f2_pack(x.x, x.x);
            u64 xb = f2_pack(x.y, x.y);
            #pragma unroll
            for (int p = 0; p < 8; p++) {
                acc[p][0] = f2_fma(xa, RsP[vv][p], acc[p][0]);
                acc[p][1] = f2_fma(xb, RsP[vv][p], acc[p][1]);
            }
        }
        #pragma unroll
        for (int p = 0; p < 8; p++) {
            float2 a = f2_unpack(acc[p][0]);
            float2 b = f2_unpack(acc[p][1]);
            dst[base2 + (size_t)(2*p)   * (TPB/2)] = h2pack(a.x, b.x);
            dst[base2 + (size_t)(2*p+1) * (TPB/2)] = h2pack(a.y, b.y);
        }
    } else {
        u64 acc[8][2];
        #pragma unroll
        for (int p = 0; p < 8; p++) { acc[p][0] = 0ULL; acc[p][1] = 0ULL; }
        #pragma unroll
        for (int vv = 0; vv < 31; vv++) {
            float2 x = h2unpack(src[base2 + (size_t)vv * (TPB/2)]);
            u64 xa = f2_pack(x.x, x.x);
            u64 xb = f2_pack(x.y, x.y);
            #pragma unroll
            for (int p = 0; p < 8; p++) {
                acc[p][0] = f2_fma(xa, RsP[vv][p + 8], acc[p][0]);
                acc[p][1] = f2_fma(xb, RsP[vv][p + 8], acc[p][1]);
            }
        }
        #pragma unroll
        for (int p = 0; p < 8; p++) {
            float2 a = f2_unpack(acc[p][0]);
            float2 b = f2_unpack(acc[p][1]);
            dst[base2 + (size_t)(2*(p + 8))     * (TPB/2)] = h2pack(a.x, b.x);
            dst[base2 + (size_t)(2*(p + 8) + 1) * (TPB/2)] = h2pack(a.y, b.y);
        }
    }
}

// ---------------------------------------------------------------------------
// Kernel 3: attention via mma.m16n8k16.f16.
// Changes vs R12 (everything else identical):
//  - ONE wait + ONE barrier after the 4-tile prefetch (smem read-only after),
//    so all 4 tiles' QK/exp/PV interleave freely across the unrolled loop.
//  - Q scaled by log2(e)/32: scores are in log2 domain, so P = 2^s comes from
//    ex2.approx.f16x2 (one MUFU op per 2 lanes) directly in fp16 A-fragment
//    form. Softmax semantics identical (exp(x) == 2^(x*log2e)).
// ---------------------------------------------------------------------------
__global__ void __launch_bounds__(256, 2)
attn_kernel(const float* __restrict__ q, float* __restrict__ out)
{
    extern __shared__ __align__(16) __half sm[];

    int u  = blockIdx.x;
    int bh = blockIdx.y;
    int tid  = threadIdx.x;
    int w    = tid >> 5;
    int lane = tid & 31;
    int gid  = lane >> 2;
    int l4   = lane & 3;
    int lj   = lane >> 3;
    int lr   = lane & 7;

    const size_t base  = (size_t)bh * NB * TPB + (size_t)u * TPB;
    const size_t base2 = base >> 1;

    u32 ks_smem = (u32)__cvta_generic_to_shared(sm);
    u32 vs_smem = ks_smem + 4 * 8192;

    u32 soff[2]; int gidx[2];
    #pragma unroll
    for (int r = 0; r < 2; r++) {
        int idx = tid + r * 256;
        int row = idx >> 3;
        int g   = (idx & 7) ^ (row & 7);
        soff[r] = (u32)(row * 128 + g * 16);
        gidx[r] = idx * 4;
    }

    const u32* ksrcs[4];
    const u32* vsrcs[4];
    ksrcs[0] = g_kre16 + base2;        vsrcs[0] = g_vre16 + base2;
    ksrcs[1] = g_kre16 + base2 + 2048; vsrcs[1] = g_vre16 + base2 + 2048;
    ksrcs[2] = g_k16 + base2;          vsrcs[2] = g_v16 + base2;
    ksrcs[3] = g_k16 + base2 + 2048;   vsrcs[3] = g_v16 + base2 + 2048;

    #pragma unroll
    for (int t = 0; t < 4; t++) {
        u32 boff = (u32)(t * 8192);
        #pragma unroll
        for (int r = 0; r < 2; r++) {
            cp_async16(ks_smem + boff + soff[r], ksrcs[t] + gidx[r]);
            cp_async16(vs_smem + boff + soff[r], vsrcs[t] + gidx[r]);
        }
    }
    cp_commit();

    // Q fragments: scale = (1/sqrt(1024)) * log2(e) -> scores in log2 domain
    const float QS = 0.045084223f;   // 1.4426950408889634f / 32
    u32 qa[4][4];
    {
        const float* q0 = q + base + (size_t)(16 * w + gid) * DHD;
        const float* q1 = q0 + 8 * DHD;
        #pragma unroll
        for (int kk = 0; kk < 4; kk++) {
            int c = 16 * kk + 2 * l4;
            float2 x0 = *(const float2*)(q0 + c);
            float2 x1 = *(const float2*)(q1 + c);
            float2 y0 = *(const float2*)(q0 + c + 8);
            float2 y1 = *(const float2*)(q1 + c + 8);
            qa[kk][0] = h2pack(x0.x * QS, x0.y * QS);
            qa[kk][1] = h2pack(x1.x * QS, x1.y * QS);
            qa[kk][2] = h2pack(y0.x * QS, y0.y * QS);
            qa[kk][3] = h2pack(y1.x * QS, y1.y * QS);
        }
    }

    float o[8][4];
    #pragma unroll
    for (int nt = 0; nt < 8; nt++)
        #pragma unroll
        for (int j = 0; j < 4; j++) o[nt][j] = 0.f;
    float l0 = 0.f, l1 = 0.f;

    // single wait + single barrier: smem is read-only afterwards
    cp_wait<0>();
    __syncthreads();

    #pragma unroll
    for (int tile = 0; tile < 4; tile++) {
        u32 ks_tile = ks_smem + tile * 8192;
        u32 vs_tile = vs_smem + tile * 8192;

        float s[8][4];
        #pragma unroll
        for (int nt = 0; nt < 8; nt++)
            #pragma unroll
            for (int j = 0; j < 4; j++) s[nt][j] = 0.f;

        #pragma unroll
        for (int ntp = 0; ntp < 4; ntp++) {
            int row = 8 * (2 * ntp + (lj >> 1)) + lr;
            u32 rbase = ks_tile + row * 128;
            int rx = row & 7;
            #pragma unroll
            for (int kk = 0; kk < 4; kk++) {
                u32 g = (u32)((2 * kk + (lj & 1)) ^ rx);
                u32 b0, b1, b2, b3;
                ldsm_x4(b0, b1, b2, b3, rbase + g * 16);
                mma_f16(s[2*ntp][0],   s[2*ntp][1],   s[2*ntp][2],   s[2*ntp][3],
                        qa[kk][0], qa[kk][1], qa[kk][2], qa[kk][3], b0, b1);
                mma_f16(s[2*ntp+1][0], s[2*ntp+1][1], s[2*ntp+1][2], s[2*ntp+1][3],
                        qa[kk][0], qa[kk][1], qa[kk][2], qa[kk][3], b2, b3);
            }
        }

        // P = 2^S via packed fp16 ex2; accumulate denominators in f32
        u32 p[4][4];
        #pragma unroll
        for (int m = 0; m < 4; m++) {
            p[m][0] = h2ex2(h2pack(s[2*m][0],   s[2*m][1]));
            p[m][1] = h2ex2(h2pack(s[2*m][2],   s[2*m][3]));
            p[m][2] = h2ex2(h2pack(s[2*m+1][0], s[2*m+1][1]));
            p[m][3] = h2ex2(h2pack(s[2*m+1][2], s[2*m+1][3]));
            float2 a0 = h2unpack(p[m][0]);
            float2 a1 = h2unpack(p[m][1]);
            float2 a2 = h2unpack(p[m][2]);
            float2 a3 = h2unpack(p[m][3]);
            l0 += a0.x + a0.y + a2.x + a2.y;
            l1 += a1.x + a1.y + a3.x + a3.y;
        }

        #pragma unroll
        for (int ntp = 0; ntp < 4; ntp++) {
            #pragma unroll
            for (int m = 0; m < 4; m++) {
                int row = 16 * m + 8 * (lj & 1) + lr;
                u32 g = (u32)((2 * ntp + (lj >> 1)) ^ (row & 7));
                u32 b0, b1, b2, b3;
                ldsm_x4_t(b0, b1, b2, b3, vs_tile + row * 128 + g * 16);
                mma_f16(o[2*ntp][0],   o[2*ntp][1],   o[2*ntp][2],   o[2*ntp][3],
                        p[m][0], p[m][1], p[m][2], p[m][3], b0, b1);
                mma_f16(o[2*ntp+1][0], o[2*ntp+1][1], o[2*ntp+1][2], o[2*ntp+1][3],
                        p[m][0], p[m][1], p[m][2], p[m][3], b2, b3);
            }
        }
    }

    l0 += __shfl_xor_sync(0xffffffffu, l0, 1);
    l0 += __shfl_xor_sync(0xffffffffu, l0, 2);
    l1 += __shfl_xor_sync(0xffffffffu, l1, 1);
    l1 += __shfl_xor_sync(0xffffffffu, l1, 2);
    float inv0 = 1.f / l0;
    float inv1 = 1.f / l1;

    float* o0 = out + base + (size_t)(16 * w + gid) * DHD;
    float* o1 = o0 + 8 * DHD;
    #pragma unroll
    for (int nt = 0; nt < 8; nt++) {
        int c = 8 * nt + 2 * l4;
        *(float2*)(o0 + c) = make_float2(o[nt][0] * inv0, o[nt][1] * inv0);
        *(float2*)(o1 + c) = make_float2(o[nt][2] * inv1, o[nt][3] * inv1);
    }
}

#define SMEM_ATTN (4 * 8192 * 2)   // 65536 bytes

// ---------------------------------------------------------------------------
extern "C" void kernel_launch(void* const* d_in, const int* in_sizes, int n_in,
                              void* d_out, int out_size)
{
    const float* q   = (const float*)d_in[0];
    const float* k   = (const float*)d_in[1];
    const float* v   = (const float*)d_in[2];
    const float* sw  = (const float*)d_in[3];
    const float* gum = (const float*)d_in[4];
    float* out = (float*)d_out;

    cudaFuncSetAttribute(attn_kernel,
                         cudaFuncAttributeMaxDynamicSharedMemorySize, SMEM_ATTN);

    dim3 g0(NB, BH);
    cvt_bucket_kernel<<<g0, 256>>>(k, v);

    sinkhorn_kernel<<<BH, 1024>>>(sw, gum);

    dim3 g2(16, BH, 4);
    permute_kernel<<<g2, 256>>>();

    dim3 g3(NB, BH);
    attn_kernel<<<g3, 256, SMEM_ATTN>>>(q, out);
}

// round 14
// speedup vs baseline: 1.4194x; 1.4194x over previous
#include <cuda_runtime.h>
#include <cuda_fp16.h>
#include <math.h>

#define BH   64      // B*H
#define NB   32      // buckets
#define BSZ  128     // tokens per bucket
#define DHD  64      // head dim
#define TPB  (BSZ*DHD)   // 8192 elems per bucket tile

typedef unsigned long long u64;
typedef unsigned int u32;

// ---- packed f32x2 helpers ----
__device__ __forceinline__ u64 f2_fma(u64 a, u64 b, u64 c) {
    u64 d; asm("fma.rn.f32x2 %0,%1,%2,%3;" : "=l"(d) : "l"(a), "l"(b), "l"(c)); return d;
}
__device__ __forceinline__ u64 f2_pack(float lo, float hi) {
    u64 d; asm("mov.b64 %0,{%1,%2};" : "=l"(d) : "f"(lo), "f"(hi)); return d;
}
__device__ __forceinline__ float2 f2_unpack(u64 v) {
    float2 r; asm("mov.b64 {%0,%1},%2;" : "=f"(r.x), "=f"(r.y) : "l"(v)); return r;
}

// ---- fp16 helpers ----
__device__ __forceinline__ u32 h2pack(float lo, float hi) {
    __half2 h = __floats2half2_rn(lo, hi);
    return *(u32*)&h;
}
__device__ __forceinline__ float2 h2unpack(u32 v) {
    __half2 h = *(__half2*)&v;
    return __half22float2(h);
}
// packed fp16 2^x (one MUFU op for two lanes)
__device__ __forceinline__ u32 h2ex2(u32 s) {
    u32 p; asm("ex2.approx.f16x2 %0,%1;" : "=r"(p) : "r"(s)); return p;
}

// ---- fp16 mma m16n8k16, f32 accumulate ----
__device__ __forceinline__ void mma_f16(float& d0, float& d1, float& d2, float& d3,
                                        u32 a0, u32 a1, u32 a2, u32 a3,
                                        u32 b0, u32 b1) {
    asm("mma.sync.aligned.m16n8k16.row.col.f32.f16.f16.f32 "
        "{%0,%1,%2,%3},{%4,%5,%6,%7},{%8,%9},{%0,%1,%2,%3};"
        : "+f"(d0), "+f"(d1), "+f"(d2), "+f"(d3)
        : "r"(a0), "r"(a1), "r"(a2), "r"(a3), "r"(b0), "r"(b1));
}

// ---- ldmatrix ----
__device__ __forceinline__ void ldsm_x4(u32& r0, u32& r1, u32& r2, u32& r3, u32 addr) {
    asm volatile("ldmatrix.sync.aligned.m8n8.x4.shared.b16 {%0,%1,%2,%3},[%4];"
                 : "=r"(r0), "=r"(r1), "=r"(r2), "=r"(r3) : "r"(addr));
}
__device__ __forceinline__ void ldsm_x4_t(u32& r0, u32& r1, u32& r2, u32& r3, u32 addr) {
    asm volatile("ldmatrix.sync.aligned.m8n8.x4.trans.shared.b16 {%0,%1,%2,%3},[%4];"
                 : "=r"(r0), "=r"(r1), "=r"(r2), "=r"(r3) : "r"(addr));
}

// ---- cp.async ----
__device__ __forceinline__ void cp_async16(u32 smem_addr, const void* gptr) {
    asm volatile("cp.async.cg.shared.global [%0], [%1], 16;"
                 :: "r"(smem_addr), "l"(gptr));
}
__device__ __forceinline__ void cp_commit() {
    asm volatile("cp.async.commit_group;");
}
template<int N> __device__ __forceinline__ void cp_wait() {
    asm volatile("cp.async.wait_group %0;" :: "n"(N));
}

// Scratch (allocation-free rule: __device__ globals). fp16 stored as packed u32.
__device__ float g_R[BH*NB*NB];
__device__ float g_bkr[BH*NB*DHD];
__device__ u32 g_k16  [(size_t)BH*NB*TPB/2];
__device__ u32 g_v16  [(size_t)BH*NB*TPB/2];
__device__ u32 g_kre16[(size_t)BH*NB*TPB/2];
__device__ u32 g_vre16[(size_t)BH*NB*TPB/2];

// ---------------------------------------------------------------------------
// Kernel 0: bucket key sums + fp16 conversion of K and V.  (R12 exact.)
// ---------------------------------------------------------------------------
__global__ void __launch_bounds__(256)
cvt_bucket_kernel(const float* __restrict__ k, const float* __restrict__ v)
{
    int u  = blockIdx.x;
    int bh = blockIdx.y;
    int tid = threadIdx.x;

    __shared__ float2 red[8][32];

    size_t base2 = (size_t)(bh * NB + u) * (TPB / 2);
    const float2* k2 = (const float2*)k + base2;
    const float2* v2 = (const float2*)v + base2;
    u32* ko = g_k16 + base2;
    u32* vo = g_v16 + base2;

    float2 s = make_float2(0.f, 0.f);
    #pragma unroll
    for (int j = 0; j < 16; j++) {
        int f = tid + j * 256;
        float2 x = k2[f];
        s.x += x.x; s.y += x.y;
        ko[f] = h2pack(x.x, x.y);
    }
    red[tid >> 5][tid & 31] = s;

    #pragma unroll
    for (int j = 0; j < 16; j++) {
        int f = tid + j * 256;
        float2 x = v2[f];
        vo[f] = h2pack(x.x, x.y);
    }
    __syncthreads();
    if (tid < 32) {
        float2 t = make_float2(0.f, 0.f);
        #pragma unroll
        for (int w = 0; w < 8; w++) { t.x += red[w][tid].x; t.y += red[w][tid].y; }
        g_bkr[(bh * NB + u) * DHD + 2 * tid]     = t.x;
        g_bkr[(bh * NB + u) * DHD + 2 * tid + 1] = t.y;
    }
}

// ---------------------------------------------------------------------------
// Kernel 1: routing -> 7 Sinkhorn iters -> exp -> strict lower tri. (R12.)
// ---------------------------------------------------------------------------
__global__ void __launch_bounds__(1024)
sinkhorn_kernel(const float* __restrict__ sort_w,
                const float* __restrict__ gum)
{
    int bh  = blockIdx.x;
    int tid = threadIdx.x;

    __shared__ float bkr[NB][DHD];
    __shared__ float ews[DHD][NB];
    __shared__ float smx[NB][NB + 1];

    int h = bh & 15;
    #pragma unroll
    for (int rep = 0; rep < 2; rep++) {
        int idx = tid + rep * 1024;
        ((float*)bkr)[idx] = g_bkr[bh * (NB * DHD) + idx];
        ((float*)ews)[idx] = sort_w[h * (DHD * NB) + idx];
    }
    __syncthreads();

    int u = tid >> 5;
    int j = tid & 31;

    float r = 0.f;
    #pragma unroll
    for (int d = 0; d < DHD; d++) r += bkr[u][d] * ews[d][j];
    r = logf(fmaxf(r, 0.f) + 1e-6f);
    r = (r + gum[bh * 1024 + tid]) * (1.0f / 0.75f);

    for (int it = 0; it < 7; it++) {
        float m = r;
        #pragma unroll
        for (int off = 16; off > 0; off >>= 1)
            m = fmaxf(m, __shfl_xor_sync(0xffffffffu, m, off));
        float se = __expf(r - m);
        #pragma unroll
        for (int off = 16; off > 0; off >>= 1)
            se += __shfl_xor_sync(0xffffffffu, se, off);
        r -= m + logf(se);

        smx[u][j] = r;
        __syncthreads();
        float cm = -3.0e38f;
        #pragma unroll
        for (int vv = 0; vv < NB; vv++) cm = fmaxf(cm, smx[vv][j]);
        float cs = 0.f;
        #pragma unroll
        for (int vv = 0; vv < NB; vv++) cs += __expf(smx[vv][j] - cm);
        r -= cm + logf(cs);
        __syncthreads();
    }

    r = __expf(r);
    if (j >= u) r = 0.f;
    g_R[bh * 1024 + tid] = r;
}

// ---------------------------------------------------------------------------
// Kernel 2: soft permutation  x_re = R @ Xmat.  (R12 exact: grid-level
// triangular split.)
// ---------------------------------------------------------------------------
__global__ void __launch_bounds__(256)
permute_kernel()
{
    int tilec = blockIdx.x;          // 0..15
    int bh    = blockIdx.y;
    int kv    = blockIdx.z & 1;      // 0 = K, 1 = V
    int half  = blockIdx.z >> 1;     // 0 = rows 0..15, 1 = rows 16..31
    int tid   = threadIdx.x;

    __shared__ u64 RsP[NB][16];      // RsP[v][p] = (R[2p][v], R[2p+1][v])
    const float* gR = g_R + bh * 1024;
    #pragma unroll
    for (int rep = 0; rep < 2; rep++) {
        int idx = tid + rep * 256;
        int vv = idx >> 4, p = idx & 15;
        RsP[vv][p] = f2_pack(gR[(2*p) * NB + vv], gR[(2*p+1) * NB + vv]);
    }
    __syncthreads();

    const u32* src = kv ? g_v16   : g_k16;
    u32*       dst = kv ? g_vre16 : g_kre16;

    size_t base2 = (size_t)bh * NB * (TPB/2) + (size_t)tilec * 256 + tid;

    if (half == 0) {
        u64 acc[8][2];
        #pragma unroll
        for (int p = 0; p < 8; p++) { acc[p][0] = 0ULL; acc[p][1] = 0ULL; }
        #pragma unroll
        for (int vv = 0; vv < 15; vv++) {
            float2 x = h2unpack(src[base2 + (size_t)vv * (TPB/2)]);
            u64 xa = f2_pack(x.x, x.x);
            u64 xb = f2_pack(x.y, x.y);
            #pragma unroll
            for (int p = 0; p < 8; p++) {
                acc[p][0] = f2_fma(xa, RsP[vv][p], acc[p][0]);
                acc[p][1] = f2_fma(xb, RsP[vv][p], acc[p][1]);
            }
        }
        #pragma unroll
        for (int p = 0; p < 8; p++) {
            float2 a = f2_unpack(acc[p][0]);
            float2 b = f2_unpack(acc[p][1]);
            dst[base2 + (size_t)(2*p)   * (TPB/2)] = h2pack(a.x, b.x);
            dst[base2 + (size_t)(2*p+1) * (TPB/2)] = h2pack(a.y, b.y);
        }
    } else {
        u64 acc[8][2];
        #pragma unroll
        for (int p = 0; p < 8; p++) { acc[p][0] = 0ULL; acc[p][1] = 0ULL; }
        #pragma unroll
        for (int vv = 0; vv < 31; vv++) {
            float2 x = h2unpack(src[base2 + (size_t)vv * (TPB/2)]);
            u64 xa = f2_pack(x.x, x.x);
            u64 xb = f2_pack(x.y, x.y);
            #pragma unroll
            for (int p = 0; p < 8; p++) {
                acc[p][0] = f2_fma(xa, RsP[vv][p + 8], acc[p][0]);
                acc[p][1] = f2_fma(xb, RsP[vv][p + 8], acc[p][1]);
            }
        }
        #pragma unroll
        for (int p = 0; p < 8; p++) {
            float2 a = f2_unpack(acc[p][0]);
            float2 b = f2_unpack(acc[p][1]);
            dst[base2 + (size_t)(2*(p + 8))     * (TPB/2)] = h2pack(a.x, b.x);
            dst[base2 + (size_t)(2*(p + 8) + 1) * (TPB/2)] = h2pack(a.y, b.y);
        }
    }
}

// ---------------------------------------------------------------------------
// Kernel 3: attention via mma.m16n8k16.f16.
// R12's staggered pipeline RESTORED (4 commit groups, progressive cp_wait,
// per-tile __syncthreads -- that structure measured 68.5us; the single-wait
// variant measured 105us). Only change kept from R13: softmax via
// ex2.approx.f16x2 with Q pre-scaled by log2(e)/32 (identical math,
// P emerges directly as the fp16 A-fragment).
// ---------------------------------------------------------------------------
__global__ void __launch_bounds__(256, 2)
attn_kernel(const float* __restrict__ q, float* __restrict__ out)
{
    extern __shared__ __align__(16) __half sm[];

    int u  = blockIdx.x;
    int bh = blockIdx.y;
    int tid  = threadIdx.x;
    int w    = tid >> 5;
    int lane = tid & 31;
    int gid  = lane >> 2;
    int l4   = lane & 3;
    int lj   = lane >> 3;
    int lr   = lane & 7;

    const size_t base  = (size_t)bh * NB * TPB + (size_t)u * TPB;
    const size_t base2 = base >> 1;

    u32 ks_smem = (u32)__cvta_generic_to_shared(sm);
    u32 vs_smem = ks_smem + 4 * 8192;

    u32 soff[2]; int gidx[2];
    #pragma unroll
    for (int r = 0; r < 2; r++) {
        int idx = tid + r * 256;
        int row = idx >> 3;
        int g   = (idx & 7) ^ (row & 7);
        soff[r] = (u32)(row * 128 + g * 16);
        gidx[r] = idx * 4;
    }

    const u32* ksrcs[4];
    const u32* vsrcs[4];
    ksrcs[0] = g_kre16 + base2;        vsrcs[0] = g_vre16 + base2;
    ksrcs[1] = g_kre16 + base2 + 2048; vsrcs[1] = g_vre16 + base2 + 2048;
    ksrcs[2] = g_k16 + base2;          vsrcs[2] = g_v16 + base2;
    ksrcs[3] = g_k16 + base2 + 2048;   vsrcs[3] = g_v16 + base2 + 2048;

    // staggered prefetch: one commit group PER TILE (R12 structure)
    #pragma unroll
    for (int t = 0; t < 4; t++) {
        u32 boff = (u32)(t * 8192);
        #pragma unroll
        for (int r = 0; r < 2; r++) {
            cp_async16(ks_smem + boff + soff[r], ksrcs[t] + gidx[r]);
            cp_async16(vs_smem + boff + soff[r], vsrcs[t] + gidx[r]);
        }
        cp_commit();
    }

    // Q fragments: scale = (1/sqrt(1024)) * log2(e) -> scores in log2 domain
    const float QS = 0.045084223f;   // 1.4426950408889634f / 32
    u32 qa[4][4];
    {
        const float* q0 = q + base + (size_t)(16 * w + gid) * DHD;
        const float* q1 = q0 + 8 * DHD;
        #pragma unroll
        for (int kk = 0; kk < 4; kk++) {
            int c = 16 * kk + 2 * l4;
            float2 x0 = *(const float2*)(q0 + c);
            float2 x1 = *(const float2*)(q1 + c);
            float2 y0 = *(const float2*)(q0 + c + 8);
            float2 y1 = *(const float2*)(q1 + c + 8);
            qa[kk][0] = h2pack(x0.x * QS, x0.y * QS);
            qa[kk][1] = h2pack(x1.x * QS, x1.y * QS);
            qa[kk][2] = h2pack(y0.x * QS, y0.y * QS);
            qa[kk][3] = h2pack(y1.x * QS, y1.y * QS);
        }
    }

    float o[8][4];
    #pragma unroll
    for (int nt = 0; nt < 8; nt++)
        #pragma unroll
        for (int j = 0; j < 4; j++) o[nt][j] = 0.f;
    float l0 = 0.f, l1 = 0.f;

    #pragma unroll
    for (int tile = 0; tile < 4; tile++) {
        switch (tile) {
            case 0: cp_wait<3>(); break;
            case 1: cp_wait<2>(); break;
            case 2: cp_wait<1>(); break;
            default: cp_wait<0>(); break;
        }
        __syncthreads();

        u32 ks_tile = ks_smem + tile * 8192;
        u32 vs_tile = vs_smem + tile * 8192;

        float s[8][4];
        #pragma unroll
        for (int nt = 0; nt < 8; nt++)
            #pragma unroll
            for (int j = 0; j < 4; j++) s[nt][j] = 0.f;

        #pragma unroll
        for (int ntp = 0; ntp < 4; ntp++) {
            int row = 8 * (2 * ntp + (lj >> 1)) + lr;
            u32 rbase = ks_tile + row * 128;
            int rx = row & 7;
            #pragma unroll
            for (int kk = 0; kk < 4; kk++) {
                u32 g = (u32)((2 * kk + (lj & 1)) ^ rx);
                u32 b0, b1, b2, b3;
                ldsm_x4(b0, b1, b2, b3, rbase + g * 16);
                mma_f16(s[2*ntp][0],   s[2*ntp][1],   s[2*ntp][2],   s[2*ntp][3],
                        qa[kk][0], qa[kk][1], qa[kk][2], qa[kk][3], b0, b1);
                mma_f16(s[2*ntp+1][0], s[2*ntp+1][1], s[2*ntp+1][2], s[2*ntp+1][3],
                        qa[kk][0], qa[kk][1], qa[kk][2], qa[kk][3], b2, b3);
            }
        }

        // P = 2^S via packed fp16 ex2; accumulate denominators in f32
        u32 p[4][4];
        #pragma unroll
        for (int m = 0; m < 4; m++) {
            p[m][0] = h2ex2(h2pack(s[2*m][0],   s[2*m][1]));
            p[m][1] = h2ex2(h2pack(s[2*m][2],   s[2*m][3]));
            p[m][2] = h2ex2(h2pack(s[2*m+1][0], s[2*m+1][1]));
            p[m][3] = h2ex2(h2pack(s[2*m+1][2], s[2*m+1][3]));
            float2 a0 = h2unpack(p[m][0]);
            float2 a1 = h2unpack(p[m][1]);
            float2 a2 = h2unpack(p[m][2]);
            float2 a3 = h2unpack(p[m][3]);
            l0 += a0.x + a0.y + a2.x + a2.y;
            l1 += a1.x + a1.y + a3.x + a3.y;
        }

        #pragma unroll
        for (int ntp = 0; ntp < 4; ntp++) {
            #pragma unroll
            for (int m = 0; m < 4; m++) {
                int row = 16 * m + 8 * (lj & 1) + lr;
                u32 g = (u32)((2 * ntp + (lj >> 1)) ^ (row & 7));
                u32 b0, b1, b2, b3;
                ldsm_x4_t(b0, b1, b2, b3, vs_tile + row * 128 + g * 16);
                mma_f16(o[2*ntp][0],   o[2*ntp][1],   o[2*ntp][2],   o[2*ntp][3],
                        p[m][0], p[m][1], p[m][2], p[m][3], b0, b1);
                mma_f16(o[2*ntp+1][0], o[2*ntp+1][1], o[2*ntp+1][2], o[2*ntp+1][3],
                        p[m][0], p[m][1], p[m][2], p[m][3], b2, b3);
            }
        }
    }

    l0 += __shfl_xor_sync(0xffffffffu, l0, 1);
    l0 += __shfl_xor_sync(0xffffffffu, l0, 2);
    l1 += __shfl_xor_sync(0xffffffffu, l1, 1);
    l1 += __shfl_xor_sync(0xffffffffu, l1, 2);
    float inv0 = 1.f / l0;
    float inv1 = 1.f / l1;

    float* o0 = out + base + (size_t)(16 * w + gid) * DHD;
    float* o1 = o0 + 8 * DHD;
    #pragma unroll
    for (int nt = 0; nt < 8; nt++) {
        int c = 8 * nt + 2 * l4;
        *(float2*)(o0 + c) = make_float2(o[nt][0] * inv0, o[nt][1] * inv0);
        *(float2*)(o1 + c) = make_float2(o[nt][2] * inv1, o[nt][3] * inv1);
    }
}

#define SMEM_ATTN (4 * 8192 * 2)   // 65536 bytes

// ---------------------------------------------------------------------------
extern "C" void kernel_launch(void* const* d_in, const int* in_sizes, int n_in,
                              void* d_out, int out_size)
{
    const float* q   = (const float*)d_in[0];
    const float* k   = (const float*)d_in[1];
    const float* v   = (const float*)d_in[2];
    const float* sw  = (const float*)d_in[3];
    const float* gum = (const float*)d_in[4];
    float* out = (float*)d_out;

    cudaFuncSetAttribute(attn_kernel,
                         cudaFuncAttributeMaxDynamicSharedMemorySize, SMEM_ATTN);

    dim3 g0(NB, BH);
    cvt_bucket_kernel<<<g0, 256>>>(k, v);

    sinkhorn_kernel<<<BH, 1024>>>(sw, gum);

    dim3 g2(16, BH, 4);
    permute_kernel<<<g2, 256>>>();

    dim3 g3(NB, BH);
    attn_kernel<<<g3, 256, SMEM_ATTN>>>(q, out);
}

// round 15
// speedup vs baseline: 1.4564x; 1.0260x over previous
#include <cuda_runtime.h>
#include <cuda_fp16.h>
#include <math.h>

#define BH   64      // B*H
#define NB   32      // buckets
#define BSZ  128     // tokens per bucket
#define DHD  64      // head dim
#define TPB  (BSZ*DHD)   // 8192 elems per bucket tile

typedef unsigned long long u64;
typedef unsigned int u32;

// ---- packed f32x2 helpers ----
__device__ __forceinline__ u64 f2_fma(u64 a, u64 b, u64 c) {
    u64 d; asm("fma.rn.f32x2 %0,%1,%2,%3;" : "=l"(d) : "l"(a), "l"(b), "l"(c)); return d;
}
__device__ __forceinline__ u64 f2_pack(float lo, float hi) {
    u64 d; asm("mov.b64 %0,{%1,%2};" : "=l"(d) : "f"(lo), "f"(hi)); return d;
}
__device__ __forceinline__ float2 f2_unpack(u64 v) {
    float2 r; asm("mov.b64 {%0,%1},%2;" : "=f"(r.x), "=f"(r.y) : "l"(v)); return r;
}

// ---- fp16 helpers ----
__device__ __forceinline__ u32 h2pack(float lo, float hi) {
    __half2 h = __floats2half2_rn(lo, hi);
    return *(u32*)&h;
}
__device__ __forceinline__ float2 h2unpack(u32 v) {
    __half2 h = *(__half2*)&v;
    return __half22float2(h);
}

// ---- fp16 mma m16n8k16, f32 accumulate ----
__device__ __forceinline__ void mma_f16(float& d0, float& d1, float& d2, float& d3,
                                        u32 a0, u32 a1, u32 a2, u32 a3,
                                        u32 b0, u32 b1) {
    asm("mma.sync.aligned.m16n8k16.row.col.f32.f16.f16.f32 "
        "{%0,%1,%2,%3},{%4,%5,%6,%7},{%8,%9},{%0,%1,%2,%3};"
        : "+f"(d0), "+f"(d1), "+f"(d2), "+f"(d3)
        : "r"(a0), "r"(a1), "r"(a2), "r"(a3), "r"(b0), "r"(b1));
}

// ---- ldmatrix ----
__device__ __forceinline__ void ldsm_x4(u32& r0, u32& r1, u32& r2, u32& r3, u32 addr) {
    asm volatile("ldmatrix.sync.aligned.m8n8.x4.shared.b16 {%0,%1,%2,%3},[%4];"
                 : "=r"(r0), "=r"(r1), "=r"(r2), "=r"(r3) : "r"(addr));
}
__device__ __forceinline__ void ldsm_x4_t(u32& r0, u32& r1, u32& r2, u32& r3, u32 addr) {
    asm volatile("ldmatrix.sync.aligned.m8n8.x4.trans.shared.b16 {%0,%1,%2,%3},[%4];"
                 : "=r"(r0), "=r"(r1), "=r"(r2), "=r"(r3) : "r"(addr));
}

// ---- cp.async ----
__device__ __forceinline__ void cp_async16(u32 smem_addr, const void* gptr) {
    asm volatile("cp.async.cg.shared.global [%0], [%1], 16;"
                 :: "r"(smem_addr), "l"(gptr));
}
__device__ __forceinline__ void cp_commit() {
    asm volatile("cp.async.commit_group;");
}
template<int N> __device__ __forceinline__ void cp_wait() {
    asm volatile("cp.async.wait_group %0;" :: "n"(N));
}

// Scratch (allocation-free rule: __device__ globals). fp16 stored as packed u32.
__device__ float g_R[BH*NB*NB];
__device__ float g_bkr[BH*NB*DHD];
__device__ u32 g_k16  [(size_t)BH*NB*TPB/2];
__device__ u32 g_v16  [(size_t)BH*NB*TPB/2];
__device__ u32 g_kre16[(size_t)BH*NB*TPB/2];
__device__ u32 g_vre16[(size_t)BH*NB*TPB/2];

// ---------------------------------------------------------------------------
// Kernel 0: bucket key sums + fp16 conversion of K and V.  (R12 exact.)
// ---------------------------------------------------------------------------
__global__ void __launch_bounds__(256)
cvt_bucket_kernel(const float* __restrict__ k, const float* __restrict__ v)
{
    int u  = blockIdx.x;
    int bh = blockIdx.y;
    int tid = threadIdx.x;

    __shared__ float2 red[8][32];

    size_t base2 = (size_t)(bh * NB + u) * (TPB / 2);
    const float2* k2 = (const float2*)k + base2;
    const float2* v2 = (const float2*)v + base2;
    u32* ko = g_k16 + base2;
    u32* vo = g_v16 + base2;

    float2 s = make_float2(0.f, 0.f);
    #pragma unroll
    for (int j = 0; j < 16; j++) {
        int f = tid + j * 256;
        float2 x = k2[f];
        s.x += x.x; s.y += x.y;
        ko[f] = h2pack(x.x, x.y);
    }
    red[tid >> 5][tid & 31] = s;

    #pragma unroll
    for (int j = 0; j < 16; j++) {
        int f = tid + j * 256;
        float2 x = v2[f];
        vo[f] = h2pack(x.x, x.y);
    }
    __syncthreads();
    if (tid < 32) {
        float2 t = make_float2(0.f, 0.f);
        #pragma unroll
        for (int w = 0; w < 8; w++) { t.x += red[w][tid].x; t.y += red[w][tid].y; }
        g_bkr[(bh * NB + u) * DHD + 2 * tid]     = t.x;
        g_bkr[(bh * NB + u) * DHD + 2 * tid + 1] = t.y;
    }
}

// ---------------------------------------------------------------------------
// Kernel 1: routing -> 7 Sinkhorn iters -> exp -> strict lower tri. (R12.)
// ---------------------------------------------------------------------------
__global__ void __launch_bounds__(1024)
sinkhorn_kernel(const float* __restrict__ sort_w,
                const float* __restrict__ gum)
{
    int bh  = blockIdx.x;
    int tid = threadIdx.x;

    __shared__ float bkr[NB][DHD];
    __shared__ float ews[DHD][NB];
    __shared__ float smx[NB][NB + 1];

    int h = bh & 15;
    #pragma unroll
    for (int rep = 0; rep < 2; rep++) {
        int idx = tid + rep * 1024;
        ((float*)bkr)[idx] = g_bkr[bh * (NB * DHD) + idx];
        ((float*)ews)[idx] = sort_w[h * (DHD * NB) + idx];
    }
    __syncthreads();

    int u = tid >> 5;
    int j = tid & 31;

    float r = 0.f;
    #pragma unroll
    for (int d = 0; d < DHD; d++) r += bkr[u][d] * ews[d][j];
    r = logf(fmaxf(r, 0.f) + 1e-6f);
    r = (r + gum[bh * 1024 + tid]) * (1.0f / 0.75f);

    for (int it = 0; it < 7; it++) {
        float m = r;
        #pragma unroll
        for (int off = 16; off > 0; off >>= 1)
            m = fmaxf(m, __shfl_xor_sync(0xffffffffu, m, off));
        float se = __expf(r - m);
        #pragma unroll
        for (int off = 16; off > 0; off >>= 1)
            se += __shfl_xor_sync(0xffffffffu, se, off);
        r -= m + logf(se);

        smx[u][j] = r;
        __syncthreads();
        float cm = -3.0e38f;
        #pragma unroll
        for (int vv = 0; vv < NB; vv++) cm = fmaxf(cm, smx[vv][j]);
        float cs = 0.f;
        #pragma unroll
        for (int vv = 0; vv < NB; vv++) cs += __expf(smx[vv][j] - cm);
        r -= cm + logf(cs);
        __syncthreads();
    }

    r = __expf(r);
    if (j >= u) r = 0.f;
    g_R[bh * 1024 + tid] = r;
}

// ---------------------------------------------------------------------------
// Kernel 2: soft permutation  x_re = R @ Xmat.  (R12 exact: grid-level
// triangular split.)
// ---------------------------------------------------------------------------
__global__ void __launch_bounds__(256)
permute_kernel()
{
    int tilec = blockIdx.x;          // 0..15
    int bh    = blockIdx.y;
    int kv    = blockIdx.z & 1;      // 0 = K, 1 = V
    int half  = blockIdx.z >> 1;     // 0 = rows 0..15, 1 = rows 16..31
    int tid   = threadIdx.x;

    __shared__ u64 RsP[NB][16];      // RsP[v][p] = (R[2p][v], R[2p+1][v])
    const float* gR = g_R + bh * 1024;
    #pragma unroll
    for (int rep = 0; rep < 2; rep++) {
        int idx = tid + rep * 256;
        int vv = idx >> 4, p = idx & 15;
        RsP[vv][p] = f2_pack(gR[(2*p) * NB + vv], gR[(2*p+1) * NB + vv]);
    }
    __syncthreads();

    const u32* src = kv ? g_v16   : g_k16;
    u32*       dst = kv ? g_vre16 : g_kre16;

    size_t base2 = (size_t)bh * NB * (TPB/2) + (size_t)tilec * 256 + tid;

    if (half == 0) {
        u64 acc[8][2];
        #pragma unroll
        for (int p = 0; p < 8; p++) { acc[p][0] = 0ULL; acc[p][1] = 0ULL; }
        #pragma unroll
        for (int vv = 0; vv < 15; vv++) {
            float2 x = h2unpack(src[base2 + (size_t)vv * (TPB/2)]);
            u64 xa = f2_pack(x.x, x.x);
            u64 xb = f2_pack(x.y, x.y);
            #pragma unroll
            for (int p = 0; p < 8; p++) {
                acc[p][0] = f2_fma(xa, RsP[vv][p], acc[p][0]);
                acc[p][1] = f2_fma(xb, RsP[vv][p], acc[p][1]);
            }
        }
        #pragma unroll
        for (int p = 0; p < 8; p++) {
            float2 a = f2_unpack(acc[p][0]);
            float2 b = f2_unpack(acc[p][1]);
            dst[base2 + (size_t)(2*p)   * (TPB/2)] = h2pack(a.x, b.x);
            dst[base2 + (size_t)(2*p+1) * (TPB/2)] = h2pack(a.y, b.y);
        }
    } else {
        u64 acc[8][2];
        #pragma unroll
        for (int p = 0; p < 8; p++) { acc[p][0] = 0ULL; acc[p][1] = 0ULL; }
        #pragma unroll
        for (int vv = 0; vv < 31; vv++) {
            float2 x = h2unpack(src[base2 + (size_t)vv * (TPB/2)]);
            u64 xa = f2_pack(x.x, x.x);
            u64 xb = f2_pack(x.y, x.y);
            #pragma unroll
            for (int p = 0; p < 8; p++) {
                acc[p][0] = f2_fma(xa, RsP[vv][p + 8], acc[p][0]);
                acc[p][1] = f2_fma(xb, RsP[vv][p + 8], acc[p][1]);
            }
        }
        #pragma unroll
        for (int p = 0; p < 8; p++) {
            float2 a = f2_unpack(acc[p][0]);
            float2 b = f2_unpack(acc[p][1]);
            dst[base2 + (size_t)(2*(p + 8))     * (TPB/2)] = h2pack(a.x, b.x);
            dst[base2 + (size_t)(2*(p + 8) + 1) * (TPB/2)] = h2pack(a.y, b.y);
        }
    }
}

// ---------------------------------------------------------------------------
// Kernel 3: attention via mma.m16n8k16.f16.
// R12 arithmetic exactly (__expf softmax, Q scale 1/32, fp16 P pack).
// ONE structural delta vs R12: two-stage consumption -- cp_wait<2> + sync,
// process tiles 0..1; cp_wait<0> + sync, process tiles 2..3. Halves the
// block-wide barriers while keeping the staggered 4-group prefetch (the R13
// failure required waiting on ALL groups before any compute; this doesn't).
// ---------------------------------------------------------------------------
__global__ void __launch_bounds__(256, 2)
attn_kernel(const float* __restrict__ q, float* __restrict__ out)
{
    extern __shared__ __align__(16) __half sm[];

    int u  = blockIdx.x;
    int bh = blockIdx.y;
    int tid  = threadIdx.x;
    int w    = tid >> 5;
    int lane = tid & 31;
    int gid  = lane >> 2;
    int l4   = lane & 3;
    int lj   = lane >> 3;
    int lr   = lane & 7;

    const size_t base  = (size_t)bh * NB * TPB + (size_t)u * TPB;
    const size_t base2 = base >> 1;

    u32 ks_smem = (u32)__cvta_generic_to_shared(sm);
    u32 vs_smem = ks_smem + 4 * 8192;

    u32 soff[2]; int gidx[2];
    #pragma unroll
    for (int r = 0; r < 2; r++) {
        int idx = tid + r * 256;
        int row = idx >> 3;
        int g   = (idx & 7) ^ (row & 7);
        soff[r] = (u32)(row * 128 + g * 16);
        gidx[r] = idx * 4;
    }

    const u32* ksrcs[4];
    const u32* vsrcs[4];
    ksrcs[0] = g_kre16 + base2;        vsrcs[0] = g_vre16 + base2;
    ksrcs[1] = g_kre16 + base2 + 2048; vsrcs[1] = g_vre16 + base2 + 2048;
    ksrcs[2] = g_k16 + base2;          vsrcs[2] = g_v16 + base2;
    ksrcs[3] = g_k16 + base2 + 2048;   vsrcs[3] = g_v16 + base2 + 2048;

    // staggered prefetch: one commit group PER TILE (R12 structure)
    #pragma unroll
    for (int t = 0; t < 4; t++) {
        u32 boff = (u32)(t * 8192);
        #pragma unroll
        for (int r = 0; r < 2; r++) {
            cp_async16(ks_smem + boff + soff[r], ksrcs[t] + gidx[r]);
            cp_async16(vs_smem + boff + soff[r], vsrcs[t] + gidx[r]);
        }
        cp_commit();
    }

    // Q fragments (fp16, scale 1/32 folded) -- R12 exact
    u32 qa[4][4];
    {
        const float* q0 = q + base + (size_t)(16 * w + gid) * DHD;
        const float* q1 = q0 + 8 * DHD;
        #pragma unroll
        for (int kk = 0; kk < 4; kk++) {
            int c = 16 * kk + 2 * l4;
            float2 x0 = *(const float2*)(q0 + c);
            float2 x1 = *(const float2*)(q1 + c);
            float2 y0 = *(const float2*)(q0 + c + 8);
            float2 y1 = *(const float2*)(q1 + c + 8);
            qa[kk][0] = h2pack(x0.x * 0.03125f, x0.y * 0.03125f);
            qa[kk][1] = h2pack(x1.x * 0.03125f, x1.y * 0.03125f);
            qa[kk][2] = h2pack(y0.x * 0.03125f, y0.y * 0.03125f);
            qa[kk][3] = h2pack(y1.x * 0.03125f, y1.y * 0.03125f);
        }
    }

    float o[8][4];
    #pragma unroll
    for (int nt = 0; nt < 8; nt++)
        #pragma unroll
        for (int j = 0; j < 4; j++) o[nt][j] = 0.f;
    float l0 = 0.f, l1 = 0.f;

    #pragma unroll
    for (int stage = 0; stage < 2; stage++) {
        if (stage == 0) cp_wait<2>(); else cp_wait<0>();
        __syncthreads();

        #pragma unroll
        for (int tt = 0; tt < 2; tt++) {
            int tile = stage * 2 + tt;
            u32 ks_tile = ks_smem + tile * 8192;
            u32 vs_tile = vs_smem + tile * 8192;

            float s[8][4];
            #pragma unroll
            for (int nt = 0; nt < 8; nt++)
                #pragma unroll
                for (int j = 0; j < 4; j++) s[nt][j] = 0.f;

            #pragma unroll
            for (int ntp = 0; ntp < 4; ntp++) {
                int row = 8 * (2 * ntp + (lj >> 1)) + lr;
                u32 rbase = ks_tile + row * 128;
                int rx = row & 7;
                #pragma unroll
                for (int kk = 0; kk < 4; kk++) {
                    u32 g = (u32)((2 * kk + (lj & 1)) ^ rx);
                    u32 b0, b1, b2, b3;
                    ldsm_x4(b0, b1, b2, b3, rbase + g * 16);
                    mma_f16(s[2*ntp][0],   s[2*ntp][1],   s[2*ntp][2],   s[2*ntp][3],
                            qa[kk][0], qa[kk][1], qa[kk][2], qa[kk][3], b0, b1);
                    mma_f16(s[2*ntp+1][0], s[2*ntp+1][1], s[2*ntp+1][2], s[2*ntp+1][3],
                            qa[kk][0], qa[kk][1], qa[kk][2], qa[kk][3], b2, b3);
                }
            }

            // P = exp(S) in f32 (independent MUFUs), pack to fp16 A-fragments
            u32 p[4][4];
            #pragma unroll
            for (int m = 0; m < 4; m++) {
                float e00 = __expf(s[2*m][0]),   e01 = __expf(s[2*m][1]);
                float e02 = __expf(s[2*m][2]),   e03 = __expf(s[2*m][3]);
                float e10 = __expf(s[2*m+1][0]), e11 = __expf(s[2*m+1][1]);
                float e12 = __expf(s[2*m+1][2]), e13 = __expf(s[2*m+1][3]);
                l0 += e00 + e01 + e10 + e11;
                l1 += e02 + e03 + e12 + e13;
                p[m][0] = h2pack(e00, e01);
                p[m][1] = h2pack(e02, e03);
                p[m][2] = h2pack(e10, e11);
                p[m][3] = h2pack(e12, e13);
            }

            #pragma unroll
            for (int ntp = 0; ntp < 4; ntp++) {
                #pragma unroll
                for (int m = 0; m < 4; m++) {
                    int row = 16 * m + 8 * (lj & 1) + lr;
                    u32 g = (u32)((2 * ntp + (lj >> 1)) ^ (row & 7));
                    u32 b0, b1, b2, b3;
                    ldsm_x4_t(b0, b1, b2, b3, vs_tile + row * 128 + g * 16);
                    mma_f16(o[2*ntp][0],   o[2*ntp][1],   o[2*ntp][2],   o[2*ntp][3],
                            p[m][0], p[m][1], p[m][2], p[m][3], b0, b1);
                    mma_f16(o[2*ntp+1][0], o[2*ntp+1][1], o[2*ntp+1][2], o[2*ntp+1][3],
                            p[m][0], p[m][1], p[m][2], p[m][3], b2, b3);
                }
            }
        }
    }

    l0 += __shfl_xor_sync(0xffffffffu, l0, 1);
    l0 += __shfl_xor_sync(0xffffffffu, l0, 2);
    l1 += __shfl_xor_sync(0xffffffffu, l1, 1);
    l1 += __shfl_xor_sync(0xffffffffu, l1, 2);
    float inv0 = 1.f / l0;
    float inv1 = 1.f / l1;

    float* o0 = out + base + (size_t)(16 * w + gid) * DHD;
    float* o1 = o0 + 8 * DHD;
    #pragma unroll
    for (int nt = 0; nt < 8; nt++) {
        int c = 8 * nt + 2 * l4;
        *(float2*)(o0 + c) = make_float2(o[nt][0] * inv0, o[nt][1] * inv0);
        *(float2*)(o1 + c) = make_float2(o[nt][2] * inv1, o[nt][3] * inv1);
    }
}

#define SMEM_ATTN (4 * 8192 * 2)   // 65536 bytes

// ---------------------------------------------------------------------------
extern "C" void kernel_launch(void* const* d_in, const int* in_sizes, int n_in,
                              void* d_out, int out_size)
{
    const float* q   = (const float*)d_in[0];
    const float* k   = (const float*)d_in[1];
    const float* v   = (const float*)d_in[2];
    const float* sw  = (const float*)d_in[3];
    const float* gum = (const float*)d_in[4];
    float* out = (float*)d_out;

    cudaFuncSetAttribute(attn_kernel,
                         cudaFuncAttributeMaxDynamicSharedMemorySize, SMEM_ATTN);

    dim3 g0(NB, BH);
    cvt_bucket_kernel<<<g0, 256>>>(k, v);

    sinkhorn_kernel<<<BH, 1024>>>(sw, gum);

    dim3 g2(16, BH, 4);
    permute_kernel<<<g2, 256>>>();

    dim3 g3(NB, BH);
    attn_kernel<<<g3, 256, SMEM_ATTN>>>(q, out);
}